// round 7
// baseline (speedup 1.0000x reference)
#include <cuda_runtime.h>
#include <cuda_bf16.h>
#include <math.h>

// Problem constants (fixed by setup_inputs)
#define B_   8
#define LK_  4
#define D_   64
#define L_   4096
#define DEPTH_ 12
#define NQ_  (B_ * LK_)   // 32

// Scratch (static device globals — no runtime allocation)
__device__ float g_s[NQ_ * L_];        // s[b*4+k][leaf]  (512 KB)
__device__ float g_nll[DEPTH_ * NQ_];  // nll[level][bk]

// ---------------------------------------------------------------------------
// Kernel 1: s[b,k,i] = (q[b,k] . leafs[b,i] . v[b,k]) / 64  for all leaves.
// One warp per leaf, 8 warps/block, fully coalesced streaming LDG.128.
// launch_bounds(256,6): cap regs at 42 -> 6 blocks/SM (75% occ) for more
// in-flight sectors. Unroll 4 keeps live ranges small (MLP=4/warp x 48
// warps/SM covers DRAM latency at the per-SM bandwidth share).
// ---------------------------------------------------------------------------
__global__ __launch_bounds__(256, 6) void k_leaf_dots(
    const float* __restrict__ q,
    const float* __restrict__ v,
    const float* __restrict__ leafs)
{
    __shared__ float qt[D_ * LK_];  // [d][k], 1 KB

    const int b   = blockIdx.x >> 9;          // 512 blocks per batch
    const int tid = threadIdx.x;

    {
        int d = tid >> 2, k = tid & 3;
        qt[tid] = q[((b << 2) + k) * D_ + d] * (1.0f / 64.0f);
    }

    const int lane = tid & 31;
    const int wid  = tid >> 5;
    const int e0   = (lane & 15) << 2;   // column base: constant per lane
    const int hi   = lane >> 4;          // row parity offset

    const float4 v0 = *(const float4*)&v[((b << 2) + 0) * D_ + e0];
    const float4 v1 = *(const float4*)&v[((b << 2) + 1) * D_ + e0];
    const float4 v2 = *(const float4*)&v[((b << 2) + 2) * D_ + e0];
    const float4 v3 = *(const float4*)&v[((b << 2) + 3) * D_ + e0];

    __syncthreads();

    const int leaf = ((blockIdx.x & 511) << 3) + wid;   // 0..4095 within batch
    const float4* mp =
        (const float4*)(leafs + (((size_t)b << 12) + (size_t)leaf) * (D_ * D_)) + lane;

    float a0 = 0.f, a1 = 0.f, a2 = 0.f, a3 = 0.f;

    #pragma unroll 4
    for (int c = 0; c < 32; ++c) {
        const float4 m  = __ldcs(mp + c * 32);                 // streaming: zero reuse
        const float4 qv = *(const float4*)&qt[(((c << 1) + hi) << 2)];

        float d0 = m.x * v0.x; d0 = fmaf(m.y, v0.y, d0); d0 = fmaf(m.z, v0.z, d0); d0 = fmaf(m.w, v0.w, d0);
        float d1 = m.x * v1.x; d1 = fmaf(m.y, v1.y, d1); d1 = fmaf(m.z, v1.z, d1); d1 = fmaf(m.w, v1.w, d1);
        float d2 = m.x * v2.x; d2 = fmaf(m.y, v2.y, d2); d2 = fmaf(m.z, v2.z, d2); d2 = fmaf(m.w, v2.w, d2);
        float d3 = m.x * v3.x; d3 = fmaf(m.y, v3.y, d3); d3 = fmaf(m.z, v3.z, d3); d3 = fmaf(m.w, v3.w, d3);

        a0 = fmaf(qv.x, d0, a0);
        a1 = fmaf(qv.y, d1, a1);
        a2 = fmaf(qv.z, d2, a2);
        a3 = fmaf(qv.w, d3, a3);
    }

    #pragma unroll
    for (int o = 16; o; o >>= 1) {
        a0 += __shfl_xor_sync(0xffffffffu, a0, o);
        a1 += __shfl_xor_sync(0xffffffffu, a1, o);
        a2 += __shfl_xor_sync(0xffffffffu, a2, o);
        a3 += __shfl_xor_sync(0xffffffffu, a3, o);
    }

    if (lane == 0) {
        const int base = (b << 2);
        g_s[((size_t)(base + 0) << 12) + leaf] = a0;
        g_s[((size_t)(base + 1) << 12) + leaf] = a1;
        g_s[((size_t)(base + 2) << 12) + leaf] = a2;
        g_s[((size_t)(base + 3) << 12) + leaf] = a3;
    }
}

// ---------------------------------------------------------------------------
// Kernel 2 (flattened): one block per (bk, level) — 384 independent blocks.
// Level-l logit n = mean of leaves [n*2^l, (n+1)*2^l); computed by `level`
// pairwise-halving steps, then logsumexp. g_s rows get 12x L2 reuse.
// ---------------------------------------------------------------------------
__global__ __launch_bounds__(256) void k_levels_flat(const int* __restrict__ e32) {
    __shared__ float bufA[L_];       // 16 KB
    __shared__ float bufB[L_ / 2];   //  8 KB
    __shared__ float red[8];
    __shared__ float bc;
    __shared__ int   s_lab;

    const int bk    = blockIdx.x & 31;
    const int level = blockIdx.x >> 5;   // 0..11
    const int tid   = threadIdx.x;

    // Warp 0: decode this block's label (int64 vs int32 storage detection)
    if (tid < 32) {
        unsigned nz = __ballot_sync(0xffffffffu, e32[2 * tid + 1] != 0);
        if (tid == 0) s_lab = (nz == 0) ? e32[2 * bk] : e32[bk];
    }

    // Load the s row (vectorized)
    const float4* srow = (const float4*)(g_s + ((size_t)bk << 12));
    float4* b4 = (float4*)bufA;
    #pragma unroll 4
    for (int i = tid; i < L_ / 4; i += 256) b4[i] = srow[i];
    __syncthreads();

    // Halve `level` times: parent = mean of children
    float* cur = bufA;
    float* nxt = bufB;
    int N = L_;
    for (int s = 0; s < level; ++s) {
        const int half = N >> 1;
        for (int i = tid; i < half; i += 256)
            nxt[i] = 0.5f * (cur[2 * i] + cur[2 * i + 1]);
        __syncthreads();
        float* t = cur; cur = nxt; nxt = t;
        N = half;
    }

    // --- block max ---
    float mx = -3.4e38f;
    for (int i = tid; i < N; i += 256) mx = fmaxf(mx, cur[i]);
    #pragma unroll
    for (int o = 16; o; o >>= 1) mx = fmaxf(mx, __shfl_xor_sync(0xffffffffu, mx, o));
    if ((tid & 31) == 0) red[tid >> 5] = mx;
    __syncthreads();
    if (tid == 0) {
        float m = red[0];
        #pragma unroll
        for (int w = 1; w < 8; ++w) m = fmaxf(m, red[w]);
        bc = m;
    }
    __syncthreads();
    mx = bc;

    // --- block sum of exp ---
    float sum = 0.f;
    for (int i = tid; i < N; i += 256) sum += __expf(cur[i] - mx);
    #pragma unroll
    for (int o = 16; o; o >>= 1) sum += __shfl_xor_sync(0xffffffffu, sum, o);
    __syncthreads();
    if ((tid & 31) == 0) red[tid >> 5] = sum;
    __syncthreads();
    if (tid == 0) {
        float s = 0.f;
        #pragma unroll
        for (int w = 0; w < 8; ++w) s += red[w];
        g_nll[level * NQ_ + bk] = mx + __logf(s) - cur[s_lab >> level];
    }
}

// ---------------------------------------------------------------------------
// Kernel 3: weighted cross-entropy reduction, latency-optimized.
// w /= w.sum() cancels in per_q = Σ_b(wy·nll)/Σ_b(wy), so only counts at the
// 32 label positions are needed: w_raw = 32/(count+1e-8).
// ---------------------------------------------------------------------------
__global__ __launch_bounds__(384) void k_final(const int* __restrict__ e32,
                                               float* __restrict__ out) {
    __shared__ float s_nll[DEPTH_ * NQ_];  // 384 floats
    __shared__ int   s_lab[NQ_];
    __shared__ float s_part[48];

    const int tid = threadIdx.x;

    s_nll[tid] = g_nll[tid];               // one coalesced LDG per thread

    if (tid < 32) {
        unsigned nz = __ballot_sync(0xffffffffu, e32[2 * tid + 1] != 0);
        s_lab[tid] = (nz == 0) ? e32[2 * tid] : e32[tid];
    }
    __syncthreads();

    if (tid < 48) {
        const int level = tid >> 2;
        const int k     = tid & 3;
        float num = 0.f, den = 0.f;
        #pragma unroll
        for (int b = 0; b < B_; ++b) {
            const int my = s_lab[(b << 2) + k] >> level;
            int cnt = 0;
            #pragma unroll
            for (int t = 0; t < NQ_; ++t) cnt += ((s_lab[t] >> level) == my);
            const float w = 32.0f / ((float)cnt + 1e-8f);
            num = fmaf(w, s_nll[level * NQ_ + (b << 2) + k], num);
            den += w;
        }
        s_part[tid] = num / den;
    }
    __syncthreads();

    if (tid == 0) {
        float total = 0.f;
        #pragma unroll
        for (int i = 0; i < 48; ++i) total += s_part[i];
        out[0] = total;
    }
}

// ---------------------------------------------------------------------------
extern "C" void kernel_launch(void* const* d_in, const int* in_sizes, int n_in,
                              void* d_out, int out_size) {
    const float* q        = (const float*)d_in[0];
    const float* v        = (const float*)d_in[1];
    const int*   expected = (const int*)d_in[2];
    const float* leafs    = (const float*)d_in[3];
    float*       out      = (float*)d_out;

    k_leaf_dots<<<(B_ * L_) / 8, 256>>>(q, v, leafs);
    k_levels_flat<<<NQ_ * DEPTH_, 256>>>(expected);
    k_final<<<1, 384>>>(expected, out);
}

// round 8
// speedup vs baseline: 1.2031x; 1.2031x over previous
#include <cuda_runtime.h>
#include <cuda_bf16.h>
#include <math.h>

// Problem constants (fixed by setup_inputs)
#define B_   8
#define LK_  4
#define D_   64
#define L_   4096
#define DEPTH_ 12
#define NQ_  (B_ * LK_)   // 32

// Scratch (static device global — no runtime allocation)
__device__ float g_s[NQ_ * L_];        // s[b*4+k][leaf]  (512 KB)

// ---------------------------------------------------------------------------
// Kernel 1: s[b,k,i] = (q[b,k] . leafs[b,i] . v[b,k]) / 64  for all leaves.
// One warp per leaf, 8 warps/block, fully coalesced streaming LDG.128.
// R5-proven config: unroll 8, 48 regs, 5 blocks/SM -> 79% DRAM, 83.6 us.
// (R6/R7 lesson: capping regs/raising occupancy cut per-warp MLP and
//  regressed DRAM% -- do NOT reintroduce __launch_bounds__ min-blocks.)
// Also zero-initializes out[0] (block 0) for the atomic reduction downstream.
// ---------------------------------------------------------------------------
__global__ __launch_bounds__(256) void k_leaf_dots(
    const float* __restrict__ q,
    const float* __restrict__ v,
    const float* __restrict__ leafs,
    float* __restrict__ out)
{
    __shared__ float qt[D_ * LK_];  // [d][k], 1 KB

    const int b   = blockIdx.x >> 9;          // 512 blocks per batch
    const int tid = threadIdx.x;

    if (blockIdx.x == 0 && tid == 0) out[0] = 0.0f;  // init for atomics

    {
        int d = tid >> 2, k = tid & 3;
        qt[tid] = q[((b << 2) + k) * D_ + d] * (1.0f / 64.0f);
    }

    const int lane = tid & 31;
    const int wid  = tid >> 5;
    const int e0   = (lane & 15) << 2;   // column base: constant per lane
    const int hi   = lane >> 4;          // row parity offset

    const float4 v0 = *(const float4*)&v[((b << 2) + 0) * D_ + e0];
    const float4 v1 = *(const float4*)&v[((b << 2) + 1) * D_ + e0];
    const float4 v2 = *(const float4*)&v[((b << 2) + 2) * D_ + e0];
    const float4 v3 = *(const float4*)&v[((b << 2) + 3) * D_ + e0];

    __syncthreads();

    const int leaf = ((blockIdx.x & 511) << 3) + wid;   // 0..4095 within batch
    const float4* mp =
        (const float4*)(leafs + (((size_t)b << 12) + (size_t)leaf) * (D_ * D_)) + lane;

    float a0 = 0.f, a1 = 0.f, a2 = 0.f, a3 = 0.f;

    #pragma unroll 8
    for (int c = 0; c < 32; ++c) {
        const float4 m  = __ldcs(mp + c * 32);                 // streaming: zero reuse
        const float4 qv = *(const float4*)&qt[(((c << 1) + hi) << 2)];

        float d0 = m.x * v0.x; d0 = fmaf(m.y, v0.y, d0); d0 = fmaf(m.z, v0.z, d0); d0 = fmaf(m.w, v0.w, d0);
        float d1 = m.x * v1.x; d1 = fmaf(m.y, v1.y, d1); d1 = fmaf(m.z, v1.z, d1); d1 = fmaf(m.w, v1.w, d1);
        float d2 = m.x * v2.x; d2 = fmaf(m.y, v2.y, d2); d2 = fmaf(m.z, v2.z, d2); d2 = fmaf(m.w, v2.w, d2);
        float d3 = m.x * v3.x; d3 = fmaf(m.y, v3.y, d3); d3 = fmaf(m.z, v3.z, d3); d3 = fmaf(m.w, v3.w, d3);

        a0 = fmaf(qv.x, d0, a0);
        a1 = fmaf(qv.y, d1, a1);
        a2 = fmaf(qv.z, d2, a2);
        a3 = fmaf(qv.w, d3, a3);
    }

    #pragma unroll
    for (int o = 16; o; o >>= 1) {
        a0 += __shfl_xor_sync(0xffffffffu, a0, o);
        a1 += __shfl_xor_sync(0xffffffffu, a1, o);
        a2 += __shfl_xor_sync(0xffffffffu, a2, o);
        a3 += __shfl_xor_sync(0xffffffffu, a3, o);
    }

    if (lane == 0) {
        const int base = (b << 2);
        g_s[((size_t)(base + 0) << 12) + leaf] = a0;
        g_s[((size_t)(base + 1) << 12) + leaf] = a1;
        g_s[((size_t)(base + 2) << 12) + leaf] = a2;
        g_s[((size_t)(base + 3) << 12) + leaf] = a3;
    }
}

// ---------------------------------------------------------------------------
// Kernel 2 (flattened + fused epilogue): one block per (bk, level), 384
// blocks. Level-l logit n = mean of the 2^l leaves in group n (pairwise
// halving), then logsumexp -> nll. The class-weight normalization cancels in
// per_q = sum_b(w*nll)/sum_b(w), so each block computes its raw weight
// w = 32/(cnt+1e-8) and the per-(level,k) denominator den = sum_b w_b from
// the 32 labels, then atomicAdd(out, w*nll/den). No separate final kernel.
// ---------------------------------------------------------------------------
__global__ __launch_bounds__(256) void k_levels_flat(const int* __restrict__ e32,
                                                     float* __restrict__ out) {
    __shared__ float bufA[L_];       // 16 KB
    __shared__ float bufB[L_ / 2];   //  8 KB
    __shared__ float red[8];
    __shared__ float bc;
    __shared__ int   s_labs[NQ_];

    const int bk    = blockIdx.x & 31;
    const int level = blockIdx.x >> 5;   // 0..11
    const int tid   = threadIdx.x;

    // Warp 0: decode ALL 32 labels (int64 vs int32 storage detection)
    if (tid < 32) {
        unsigned nz = __ballot_sync(0xffffffffu, e32[2 * tid + 1] != 0);
        s_labs[tid] = (nz == 0) ? e32[2 * tid] : e32[tid];
    }

    // Load the s row (vectorized)
    const float4* srow = (const float4*)(g_s + ((size_t)bk << 12));
    float4* b4 = (float4*)bufA;
    #pragma unroll 4
    for (int i = tid; i < L_ / 4; i += 256) b4[i] = srow[i];
    __syncthreads();

    // Halve `level` times: parent = mean of children
    float* cur = bufA;
    float* nxt = bufB;
    int N = L_;
    for (int s = 0; s < level; ++s) {
        const int half = N >> 1;
        for (int i = tid; i < half; i += 256)
            nxt[i] = 0.5f * (cur[2 * i] + cur[2 * i + 1]);
        __syncthreads();
        float* t = cur; cur = nxt; nxt = t;
        N = half;
    }

    // --- block max ---
    float mx = -3.4e38f;
    for (int i = tid; i < N; i += 256) mx = fmaxf(mx, cur[i]);
    #pragma unroll
    for (int o = 16; o; o >>= 1) mx = fmaxf(mx, __shfl_xor_sync(0xffffffffu, mx, o));
    if ((tid & 31) == 0) red[tid >> 5] = mx;
    __syncthreads();
    if (tid == 0) {
        float m = red[0];
        #pragma unroll
        for (int w = 1; w < 8; ++w) m = fmaxf(m, red[w]);
        bc = m;
    }
    __syncthreads();
    mx = bc;

    // --- block sum of exp ---
    float sum = 0.f;
    for (int i = tid; i < N; i += 256) sum += __expf(cur[i] - mx);
    #pragma unroll
    for (int o = 16; o; o >>= 1) sum += __shfl_xor_sync(0xffffffffu, sum, o);
    __syncthreads();
    if ((tid & 31) == 0) red[tid >> 5] = sum;
    __syncthreads();

    if (tid == 0) {
        float s = 0.f;
        #pragma unroll
        for (int w = 0; w < 8; ++w) s += red[w];
        const int mylab = s_labs[bk] >> level;
        const float nll = mx + __logf(s) - cur[mylab];

        // raw weight for this query's class at this level
        int cnt = 0;
        #pragma unroll
        for (int t = 0; t < NQ_; ++t) cnt += ((s_labs[t] >> level) == mylab);
        const float w = 32.0f / ((float)cnt + 1e-8f);

        // denominator: sum of raw weights over the batch for this k
        const int k = bk & 3;
        float den = 0.f;
        #pragma unroll
        for (int b = 0; b < B_; ++b) {
            const int lb = s_labs[(b << 2) + k] >> level;
            int c = 0;
            #pragma unroll
            for (int t = 0; t < NQ_; ++t) c += ((s_labs[t] >> level) == lb);
            den += 32.0f / ((float)c + 1e-8f);
        }

        atomicAdd(out, w * nll / den);
    }
}

// ---------------------------------------------------------------------------
extern "C" void kernel_launch(void* const* d_in, const int* in_sizes, int n_in,
                              void* d_out, int out_size) {
    const float* q        = (const float*)d_in[0];
    const float* v        = (const float*)d_in[1];
    const int*   expected = (const int*)d_in[2];
    const float* leafs    = (const float*)d_in[3];
    float*       out      = (float*)d_out;

    k_leaf_dots<<<(B_ * L_) / 8, 256>>>(q, v, leafs, out);
    k_levels_flat<<<NQ_ * DEPTH_, 256>>>(expected, out);
}